// round 6
// baseline (speedup 1.0000x reference)
#include <cuda_runtime.h>
#include <cstdint>

// Problem constants
#define HWDIM 9216            // H*W = 96*96
#define NB 16                 // batch
#define NPOS (HWDIM * NB)     // 147456 spatial positions
#define CIN 256
#define HCH 10                // h
#define NPARTS 6
#define PART_SZ (NPARTS * NB * HCH * HWDIM)   // 8,847,360 (fits int)
#define PBH (NB * HCH * HWDIM)                // 1,474,560

typedef unsigned long long u64;

// Pre-packed tf32 weights: 72 rows x 264 words (pair-packed for LDS.64 frags)
#define B_STRIDE 264
#define B_WORDS (72 * B_STRIDE)      // 19008
__device__ uint32_t g_Bw[B_WORDS];
__device__ float    g_bias[72];      // b_dp (0..9) | b_proj (10..69) | 0

__device__ __forceinline__ float sigm(float x) {
    return 1.0f / (1.0f + __expf(-x));
}

__device__ __forceinline__ uint32_t to_tf32(float x) {
    uint32_t r;
    asm("cvt.rna.tf32.f32 %0, %1;" : "=r"(r) : "f"(x));
    return r;
}

__device__ __forceinline__ void mma_tf32(float d[4],
                                         uint32_t a0, uint32_t a1,
                                         uint32_t a2, uint32_t a3,
                                         uint32_t b0, uint32_t b1) {
    asm volatile(
        "mma.sync.aligned.m16n8k8.row.col.f32.tf32.tf32.f32 "
        "{%0,%1,%2,%3}, {%4,%5,%6,%7}, {%8,%9}, {%0,%1,%2,%3};"
        : "+f"(d[0]), "+f"(d[1]), "+f"(d[2]), "+f"(d[3])
        : "r"(a0), "r"(a1), "r"(a2), "r"(a3), "r"(b0), "r"(b1));
}

// ---------------------------------------------------------------------------
// Prep kernel: tf32 weights (pair-packed) + fused bias vector.
// word(r, k) = r*264 + (k>>3)*8 + (k&3)*2 + ((k>>2)&1)
// ---------------------------------------------------------------------------
__global__ void prep_kernel(const float* __restrict__ w_dp_f,
                            const float* __restrict__ w_proj,
                            const float* __restrict__ b_dp,
                            const float* __restrict__ b_proj) {
    const int r = blockIdx.x;          // 0..71
    const int k = threadIdx.x;         // 0..255
    float v = 0.f;
    if (r < HCH)      v = w_dp_f[r * CIN + k];
    else if (r < 70)  v = w_proj[(r - HCH) * CIN + k];
    g_Bw[r * B_STRIDE + ((k >> 3) << 3) + (k & 3) * 2 + ((k >> 2) & 1)] = to_tf32(v);
    if (k < 8) g_Bw[r * B_STRIDE + 256 + k] = 0u;
    if (k == 0) {
        float bv = 0.f;
        if (r < HCH)     bv = b_dp[r];
        else if (r < 70) bv = b_proj[r - HCH];
        g_bias[r] = bv;
    }
}

// ---------------------------------------------------------------------------
// Fused kernel: tf32 MMA GEMM (Y = W @ p_fea for this CTA's 128 positions)
// -> D transpose to smem (+bias) -> in-CTA graph epilogue -> out.
// smem (words): B [0,19008) | A [19008,27712)  (phase 1)
//   overlay after MMA: D [0, 128*73) | stash [9344, 9344+128*37)
// 110,848 bytes -> 2 CTAs/SM.
// ---------------------------------------------------------------------------
#define A_STRIDE 136
#define A_WORDS (64 * A_STRIDE)                 // 8704
#define SM_A 19008
#define FUSED_SMEM ((B_WORDS + A_WORDS) * 4)    // 110,848 bytes
#define D_STRIDE 73
#define SM_STASH (128 * D_STRIDE)               // 9344
#define STASH_STRIDE 37
// stash per pos: att[0..5] | S0[6..15] | S1[16..25] | dp1[26..35]

extern __shared__ uint32_t sm4[];

__global__ void __launch_bounds__(256, 2)
fused_kernel(const float* __restrict__ p_fea,
             const float* __restrict__ xp_stack,
             const float* __restrict__ xh_stack,
             const float* __restrict__ w_att,  const float* __restrict__ b_att,
             const float* __restrict__ w_dp_x,
             const float* __restrict__ w_gate, const float* __restrict__ b_gate,
             const float* __restrict__ w_upd,  const float* __restrict__ b_upd,
             float* __restrict__ out) {
    float* smf = (float*)sm4;
    const int tid  = threadIdx.x;
    const int wid  = tid >> 5;
    const int lane = tid & 31;

    // ---- copy pre-packed B verbatim (uint4)
    {
        uint4* dst = (uint4*)sm4;
        const uint4* src = (const uint4*)g_Bw;
#pragma unroll
        for (int i = 0; i < 19; ++i) {
            const int idx = tid + i * 256;
            if (idx < B_WORDS / 4) dst[idx] = src[idx];
        }
    }

    const int tbase = blockIdx.x * 128;
    const int b  = tbase / HWDIM;
    const int s0 = tbase - b * HWDIM;

    // loader role
    const int lpos = tid & 127;
    const int kb   = tid >> 7;           // 0 or 1
    const float* gx = p_fea + (size_t)b * (CIN * HWDIM) + s0 + lpos;

    // MMA role
    const int mt = wid;
    const int q  = lane >> 2;
    const int rr = lane & 3;
    const int arow = mt * 16 + q;

    float d[9][4];
#pragma unroll
    for (int nt = 0; nt < 9; ++nt)
#pragma unroll
        for (int j = 0; j < 4; ++j) d[nt][j] = 0.f;

    uint32_t* Abuf = sm4 + SM_A;

    // prologue: chunk 0 -> regs -> A buffer
    float xr[32];
#pragma unroll
    for (int i = 0; i < 32; ++i)
        xr[i] = gx[(size_t)(kb + i * 2) * HWDIM];
#pragma unroll
    for (int i = 0; i < 32; ++i)
        Abuf[(kb + i * 2) * A_STRIDE + lpos] = to_tf32(xr[i]);

#pragma unroll 1
    for (int c = 0; c < 4; ++c) {
        __syncthreads();   // A chunk c (and B on c==0) visible

        if (c < 3) {
#pragma unroll
            for (int i = 0; i < 32; ++i)
                xr[i] = gx[(size_t)((c + 1) * 64 + kb + i * 2) * HWDIM];
        }

        // MMA over 8 k-steps of this chunk
#pragma unroll
        for (int ks = 0; ks < 8; ++ks) {
            const int kl = ks * 8 + rr;
            const uint32_t a0 = Abuf[kl * A_STRIDE + arow];
            const uint32_t a1 = Abuf[kl * A_STRIDE + arow + 8];
            const uint32_t a2 = Abuf[(kl + 4) * A_STRIDE + arow];
            const uint32_t a3 = Abuf[(kl + 4) * A_STRIDE + arow + 8];
            const int bbase = (c * 8 + ks) * 8 + rr * 2;
#pragma unroll
            for (int nt = 0; nt < 9; ++nt) {
                const u64 b01 = *(const u64*)(sm4 + (nt * 8 + q) * B_STRIDE + bbase);
                mma_tf32(d[nt], a0, a1, a2, a3,
                         (uint32_t)b01, (uint32_t)(b01 >> 32));
            }
        }
        __syncthreads();   // all A (and final B) reads done

        if (c < 3) {
#pragma unroll
            for (int i = 0; i < 32; ++i)
                Abuf[(kb + i * 2) * A_STRIDE + lpos] = to_tf32(xr[i]);
        }
    }

    // ---- phase 2: D -> smem (pos-major, stride 73), bias folded
    {
        const int pr = mt * 16 + q;
#pragma unroll
        for (int nt = 0; nt < 9; ++nt) {
            const int n0 = nt * 8 + rr * 2;
            const float b0 = g_bias[n0];
            const float b1 = g_bias[n0 + 1];
            smf[pr * D_STRIDE + n0]           = d[nt][0] + b0;
            smf[pr * D_STRIDE + n0 + 1]       = d[nt][1] + b1;
            smf[(pr + 8) * D_STRIDE + n0]     = d[nt][2] + b0;
            smf[(pr + 8) * D_STRIDE + n0 + 1] = d[nt][3] + b1;
        }
    }
    __syncthreads();

    // ---- phase 3: epilogue. grp0 (t<128): parts 0..2; grp1: parts 3..5.
    const int pos = tid & 127;
    const int grp = tid >> 7;
    const int p0  = grp * 3;
    const int s   = s0 + pos;
    const int bbase = b * (HCH * HWDIM) + s;
    const float* Dp = smf + pos * D_STRIDE;
    float* st = smf + SM_STASH + pos * STASH_STRIDE;

    // pass 1: per-group 3 parts
    float xq[3][10];
    float att3[3];
    float Sp[HCH];
    float dp1[HCH];
#pragma unroll
    for (int e = 0; e < HCH; ++e) Sp[e] = 0.f;

    {
        float fdp[HCH];
#pragma unroll
        for (int e = 0; e < HCH; ++e) fdp[e] = Dp[e];

#pragma unroll
        for (int i = 0; i < 3; ++i) {
            const int p = p0 + i;
            const float* xpp_ptr = xp_stack + p * PBH + bbase;
#pragma unroll
            for (int e = 0; e < HCH; ++e) xq[i][e] = xpp_ptr[e * HWDIM];

            float a = __ldg(b_att + p);
#pragma unroll
            for (int e = 0; e < HCH; ++e) a += __ldg(w_att + p * HCH + e) * xq[i][e];
            a = sigm(a);
            att3[i] = a;

            float dpv[HCH];
#pragma unroll
            for (int e = 0; e < HCH; ++e) {
                float u = fdp[e];
#pragma unroll
                for (int f = 0; f < HCH; ++f)
                    u += __ldg(w_dp_x + e * HCH + f) * xq[i][f];
                dpv[e] = fmaxf(u, 0.f);
            }
            if (p == 1) {
#pragma unroll
                for (int e = 0; e < HCH; ++e) dp1[e] = dpv[e];
            } else {
#pragma unroll
                for (int e = 0; e < HCH; ++e) Sp[e] += a * dpv[e];
            }
        }
        // stash
#pragma unroll
        for (int i = 0; i < 3; ++i) st[p0 + i] = att3[i];
#pragma unroll
        for (int e = 0; e < HCH; ++e) st[6 + grp * 10 + e] = Sp[e];
        if (grp == 0) {
#pragma unroll
            for (int e = 0; e < HCH; ++e) st[26 + e] = dp1[e];
        }
    }
    __syncthreads();

    // pass 2
    {
        float attv[6];
#pragma unroll
        for (int i = 0; i < 6; ++i) attv[i] = st[i];
        float S[HCH], dp1v[HCH];
#pragma unroll
        for (int e = 0; e < HCH; ++e) {
            S[e] = st[6 + e] + st[16 + e];
            dp1v[e] = st[26 + e];
        }
        const float att1 = attv[1];
        const float attsum = attv[0] + attv[2] + attv[3] + attv[4] + attv[5];

        // xh: grp0 parts 0..2 -> upper only; grp1: part3 upper, 4&5 lower
        float xhU[HCH], xhL[HCH];
        {
            const float* xu = xh_stack + bbase;
#pragma unroll
            for (int e = 0; e < HCH; ++e) xhU[e] = xu[e * HWDIM];
        }
        if (grp == 1) {
            const float* xl = xh_stack + PBH + bbase;
#pragma unroll
            for (int e = 0; e < HCH; ++e) xhL[e] = xl[e * HWDIM];
        }

#pragma unroll
        for (int i = 0; i < 3; ++i) {
            const int p = p0 + i;

            float xppv[HCH];
            if (p == 1) {
#pragma unroll
                for (int e = 0; e < HCH; ++e)
                    xppv[e] = att1 * (S[e] + attsum * xq[i][e]);
            } else {
                const float aa = att1 * attv[p];
#pragma unroll
                for (int e = 0; e < HCH; ++e)
                    xppv[e] = aa * (dp1v[e] + xq[i][e]);
            }

            float gsum = __ldg(b_gate + p);
            const float* xh = (p < 4) ? xhU : xhL;
#pragma unroll
            for (int e = 0; e < HCH; ++e)
                gsum += __ldg(w_gate + p * 2 * HCH + e) * xh[e];
#pragma unroll
            for (int e = 0; e < HCH; ++e)
                gsum += __ldg(w_gate + p * 2 * HCH + HCH + e) * xq[i][e];
            const float gate = sigm(gsum);

            float xhpv[HCH];
#pragma unroll
            for (int e = 0; e < HCH; ++e)
                xhpv[e] = gate * Dp[HCH + p * HCH + e];   // bias folded

            float* o0 = out + p * PBH + bbase;
#pragma unroll
            for (int e = 0; e < HCH; ++e) {
                float u = __ldg(b_upd + p * HCH + e);
                const float* wr = w_upd + (p * HCH + e) * (3 * HCH);
#pragma unroll
                for (int f = 0; f < HCH; ++f) u += __ldg(wr + f) * xq[i][f];
#pragma unroll
                for (int f = 0; f < HCH; ++f) u += __ldg(wr + HCH + f) * xppv[f];
#pragma unroll
                for (int f = 0; f < HCH; ++f) u += __ldg(wr + 2 * HCH + f) * xhpv[f];
                const float o = xq[i][e] + fmaxf(u, 0.f);

                const int doff = e * HWDIM;
                o0[doff]               = o;
                o0[PART_SZ + doff]     = xppv[e];
                o0[2 * PART_SZ + doff] = xhpv[e];
            }
        }
    }
}

// ---------------------------------------------------------------------------
extern "C" void kernel_launch(void* const* d_in, const int* in_sizes, int n_in,
                              void* d_out, int out_size) {
    const float* p_fea  = (const float*)d_in[0];
    const float* xp     = (const float*)d_in[1];
    const float* xh     = (const float*)d_in[2];
    const float* w_att  = (const float*)d_in[3];
    const float* b_att  = (const float*)d_in[4];
    const float* w_dp_f = (const float*)d_in[5];
    const float* w_dp_x = (const float*)d_in[6];
    const float* b_dp   = (const float*)d_in[7];
    const float* w_proj = (const float*)d_in[8];
    const float* b_proj = (const float*)d_in[9];
    const float* w_gate = (const float*)d_in[10];
    const float* b_gate = (const float*)d_in[11];
    const float* w_upd  = (const float*)d_in[12];
    const float* b_upd  = (const float*)d_in[13];
    float* out = (float*)d_out;

    cudaFuncSetAttribute(fused_kernel, cudaFuncAttributeMaxDynamicSharedMemorySize,
                         FUSED_SMEM);

    prep_kernel<<<72, 256>>>(w_dp_f, w_proj, b_dp, b_proj);
    fused_kernel<<<NPOS / 128, 256, FUSED_SMEM>>>(
        p_fea, xp, xh, w_att, b_att, w_dp_x, w_gate, b_gate, w_upd, b_upd, out);
}

// round 7
// speedup vs baseline: 1.0756x; 1.0756x over previous
#include <cuda_runtime.h>
#include <cstdint>

// Problem constants
#define HWDIM 9216            // H*W = 96*96
#define NB 16                 // batch
#define NPOS (HWDIM * NB)     // 147456 spatial positions
#define CIN 256
#define HCH 10                // h
#define NPARTS 6
#define PART_SZ (NPARTS * NB * HCH * HWDIM)   // 8,847,360 (fits int)
#define PBH (NB * HCH * HWDIM)                // 1,474,560

typedef unsigned long long u64;

// Pre-packed tf32 weights: 72 rows x 264 words (pair-packed for LDS.64 frags)
#define B_STRIDE 264
#define B_WORDS (72 * B_STRIDE)      // 19008
__device__ uint32_t g_Bw[B_WORDS];
__device__ float    g_bias[72];      // b_dp (0..9) | b_proj (10..69) | 0

__device__ __forceinline__ float sigm(float x) {
    return 1.0f / (1.0f + __expf(-x));
}

__device__ __forceinline__ uint32_t to_tf32(float x) {
    uint32_t r;
    asm("cvt.rna.tf32.f32 %0, %1;" : "=r"(r) : "f"(x));
    return r;
}

__device__ __forceinline__ void mma_tf32(float d[4],
                                         uint32_t a0, uint32_t a1,
                                         uint32_t a2, uint32_t a3,
                                         uint32_t b0, uint32_t b1) {
    asm volatile(
        "mma.sync.aligned.m16n8k8.row.col.f32.tf32.tf32.f32 "
        "{%0,%1,%2,%3}, {%4,%5,%6,%7}, {%8,%9}, {%0,%1,%2,%3};"
        : "+f"(d[0]), "+f"(d[1]), "+f"(d[2]), "+f"(d[3])
        : "r"(a0), "r"(a1), "r"(a2), "r"(a3), "r"(b0), "r"(b1));
}

// ---------------------------------------------------------------------------
// Prep kernel: tf32 weights (pair-packed) + fused bias vector.
// word(r, k) = r*264 + (k>>3)*8 + (k&3)*2 + ((k>>2)&1)
// ---------------------------------------------------------------------------
__global__ void prep_kernel(const float* __restrict__ w_dp_f,
                            const float* __restrict__ w_proj,
                            const float* __restrict__ b_dp,
                            const float* __restrict__ b_proj) {
    const int r = blockIdx.x;          // 0..71
    const int k = threadIdx.x;         // 0..255
    float v = 0.f;
    if (r < HCH)      v = w_dp_f[r * CIN + k];
    else if (r < 70)  v = w_proj[(r - HCH) * CIN + k];
    g_Bw[r * B_STRIDE + ((k >> 3) << 3) + (k & 3) * 2 + ((k >> 2) & 1)] = to_tf32(v);
    if (k < 8) g_Bw[r * B_STRIDE + 256 + k] = 0u;
    if (k == 0) {
        float bv = 0.f;
        if (r < HCH)     bv = b_dp[r];
        else if (r < 70) bv = b_proj[r - HCH];
        g_bias[r] = bv;
    }
}

// ---------------------------------------------------------------------------
// Fused kernel: tf32 MMA GEMM (Y = W @ p_fea for this CTA's 128 positions)
// -> D transpose to smem (+bias) + epi-weight copy -> in-CTA epilogue -> out.
// smem (words): phase 1: B [0,19008) | A [19008,27712)
//   overlay phase 2/3: D [0,9344) | stash [9344,14080) | weights [14080,16232)
// 110,848 bytes -> 2 CTAs/SM.
// ---------------------------------------------------------------------------
#define A_STRIDE 136
#define A_WORDS (64 * A_STRIDE)                 // 8704
#define SM_A 19008
#define FUSED_SMEM ((B_WORDS + A_WORDS) * 4)    // 110,848 bytes
#define D_STRIDE 73
#define SM_STASH (128 * D_STRIDE)               // 9344
#define STASH_STRIDE 37
#define SM_W (SM_STASH + 128 * STASH_STRIDE)    // 14080
#define NW_EPI 2152
// epi weight cache layout: w_att 0 | b_att 60 | w_dp_x 66 | w_gate 166 |
//                          b_gate 286 | w_upd 292 | b_upd 2092

extern __shared__ uint32_t sm4[];

__global__ void __launch_bounds__(256, 2)
fused_kernel(const float* __restrict__ p_fea,
             const float* __restrict__ xp_stack,
             const float* __restrict__ xh_stack,
             const float* __restrict__ w_att,  const float* __restrict__ b_att,
             const float* __restrict__ w_dp_x,
             const float* __restrict__ w_gate, const float* __restrict__ b_gate,
             const float* __restrict__ w_upd,  const float* __restrict__ b_upd,
             float* __restrict__ out) {
    float* smf = (float*)sm4;
    const int tid  = threadIdx.x;
    const int wid  = tid >> 5;
    const int lane = tid & 31;

    // ---- copy pre-packed B verbatim (uint4)
    {
        uint4* dst = (uint4*)sm4;
        const uint4* src = (const uint4*)g_Bw;
#pragma unroll
        for (int i = 0; i < 19; ++i) {
            const int idx = tid + i * 256;
            if (idx < B_WORDS / 4) dst[idx] = src[idx];
        }
    }

    const int tbase = blockIdx.x * 128;
    const int b  = tbase / HWDIM;
    const int s0 = tbase - b * HWDIM;

    // loader role
    const int lpos = tid & 127;
    const int kb   = tid >> 7;           // 0 or 1
    const float* gx = p_fea + (size_t)b * (CIN * HWDIM) + s0 + lpos;

    // MMA role
    const int mt = wid;
    const int q  = lane >> 2;
    const int rr = lane & 3;
    const int arow = mt * 16 + q;

    float d[9][4];
#pragma unroll
    for (int nt = 0; nt < 9; ++nt)
#pragma unroll
        for (int j = 0; j < 4; ++j) d[nt][j] = 0.f;

    uint32_t* Abuf = sm4 + SM_A;

    // prologue: chunk 0 -> regs -> A buffer
    float xr[32];
#pragma unroll
    for (int i = 0; i < 32; ++i)
        xr[i] = gx[(size_t)(kb + i * 2) * HWDIM];
#pragma unroll
    for (int i = 0; i < 32; ++i)
        Abuf[(kb + i * 2) * A_STRIDE + lpos] = to_tf32(xr[i]);

#pragma unroll 1
    for (int c = 0; c < 4; ++c) {
        __syncthreads();   // A chunk c (and B on c==0) visible

        if (c < 3) {
#pragma unroll
            for (int i = 0; i < 32; ++i)
                xr[i] = gx[(size_t)((c + 1) * 64 + kb + i * 2) * HWDIM];
        }

        // MMA over 8 k-steps of this chunk
#pragma unroll
        for (int ks = 0; ks < 8; ++ks) {
            const int kl = ks * 8 + rr;
            const uint32_t a0 = Abuf[kl * A_STRIDE + arow];
            const uint32_t a1 = Abuf[kl * A_STRIDE + arow + 8];
            const uint32_t a2 = Abuf[(kl + 4) * A_STRIDE + arow];
            const uint32_t a3 = Abuf[(kl + 4) * A_STRIDE + arow + 8];
            const int bbase = (c * 8 + ks) * 8 + rr * 2;
#pragma unroll
            for (int nt = 0; nt < 9; ++nt) {
                const u64 b01 = *(const u64*)(sm4 + (nt * 8 + q) * B_STRIDE + bbase);
                mma_tf32(d[nt], a0, a1, a2, a3,
                         (uint32_t)b01, (uint32_t)(b01 >> 32));
            }
        }
        __syncthreads();   // all A (and final B) reads done

        if (c < 3) {
#pragma unroll
            for (int i = 0; i < 32; ++i)
                Abuf[(kb + i * 2) * A_STRIDE + lpos] = to_tf32(xr[i]);
        }
    }

    // ---- phase 2: D -> smem (pos-major, stride 73, bias folded) + weight copy
    {
        const int pr = mt * 16 + q;
#pragma unroll
        for (int nt = 0; nt < 9; ++nt) {
            const int n0 = nt * 8 + rr * 2;
            const float b0 = g_bias[n0];
            const float b1 = g_bias[n0 + 1];
            smf[pr * D_STRIDE + n0]           = d[nt][0] + b0;
            smf[pr * D_STRIDE + n0 + 1]       = d[nt][1] + b1;
            smf[(pr + 8) * D_STRIDE + n0]     = d[nt][2] + b0;
            smf[(pr + 8) * D_STRIDE + n0 + 1] = d[nt][3] + b1;
        }
        // epi weights -> smem (one pass, 9 loads/thread)
        for (int i = tid; i < NW_EPI; i += 256) {
            float v;
            if      (i < 60)   v = w_att[i];
            else if (i < 66)   v = b_att[i - 60];
            else if (i < 166)  v = w_dp_x[i - 66];
            else if (i < 286)  v = w_gate[i - 166];
            else if (i < 292)  v = b_gate[i - 286];
            else if (i < 2092) v = w_upd[i - 292];
            else               v = b_upd[i - 2092];
            smf[SM_W + i] = v;
        }
    }
    __syncthreads();

    const float* sW_att  = smf + SM_W;
    const float* sB_att  = smf + SM_W + 60;
    const float* sW_dpx  = smf + SM_W + 66;
    const float* sW_gate = smf + SM_W + 166;
    const float* sB_gate = smf + SM_W + 286;
    const float* sW_upd  = smf + SM_W + 292;
    const float* sB_upd  = smf + SM_W + 2092;

    // ---- phase 3: epilogue. grp0 (t<128): parts 0..2; grp1: parts 3..5.
    const int pos = tid & 127;
    const int grp = tid >> 7;
    const int p0  = grp * 3;
    const int s   = s0 + pos;
    const int bbase = b * (HCH * HWDIM) + s;
    const float* Dp = smf + pos * D_STRIDE;
    float* st = smf + SM_STASH + pos * STASH_STRIDE;

    // pass 1: per-group 3 parts
    float xq[3][10];
    float att3[3];
    float Sp[HCH];
    float dp1[HCH];
#pragma unroll
    for (int e = 0; e < HCH; ++e) Sp[e] = 0.f;

    {
        float fdp[HCH];
#pragma unroll
        for (int e = 0; e < HCH; ++e) fdp[e] = Dp[e];

#pragma unroll
        for (int i = 0; i < 3; ++i) {
            const int p = p0 + i;
            const float* xpp_ptr = xp_stack + p * PBH + bbase;
#pragma unroll
            for (int e = 0; e < HCH; ++e) xq[i][e] = xpp_ptr[e * HWDIM];

            float a = sB_att[p];
#pragma unroll
            for (int e = 0; e < HCH; ++e) a += sW_att[p * HCH + e] * xq[i][e];
            a = sigm(a);
            att3[i] = a;

            float dpv[HCH];
#pragma unroll
            for (int e = 0; e < HCH; ++e) {
                float u = fdp[e];
#pragma unroll
                for (int f = 0; f < HCH; ++f)
                    u += sW_dpx[e * HCH + f] * xq[i][f];
                dpv[e] = fmaxf(u, 0.f);
            }
            if (p == 1) {
#pragma unroll
                for (int e = 0; e < HCH; ++e) dp1[e] = dpv[e];
            } else {
#pragma unroll
                for (int e = 0; e < HCH; ++e) Sp[e] += a * dpv[e];
            }
        }
        // stash
#pragma unroll
        for (int i = 0; i < 3; ++i) st[p0 + i] = att3[i];
#pragma unroll
        for (int e = 0; e < HCH; ++e) st[6 + grp * 10 + e] = Sp[e];
        if (grp == 0) {
#pragma unroll
            for (int e = 0; e < HCH; ++e) st[26 + e] = dp1[e];
        }
    }
    __syncthreads();

    // pass 2
    {
        float attv[6];
#pragma unroll
        for (int i = 0; i < 6; ++i) attv[i] = st[i];
        float S[HCH], dp1v[HCH];
#pragma unroll
        for (int e = 0; e < HCH; ++e) {
            S[e] = st[6 + e] + st[16 + e];
            dp1v[e] = st[26 + e];
        }
        const float att1 = attv[1];
        const float attsum = attv[0] + attv[2] + attv[3] + attv[4] + attv[5];

        // xh: grp0 parts 0..2 -> upper only; grp1: part3 upper, 4&5 lower
        float xhU[HCH], xhL[HCH];
        {
            const float* xu = xh_stack + bbase;
#pragma unroll
            for (int e = 0; e < HCH; ++e) xhU[e] = xu[e * HWDIM];
        }
        if (grp == 1) {
            const float* xl = xh_stack + PBH + bbase;
#pragma unroll
            for (int e = 0; e < HCH; ++e) xhL[e] = xl[e * HWDIM];
        }

#pragma unroll
        for (int i = 0; i < 3; ++i) {
            const int p = p0 + i;

            float xppv[HCH];
            if (p == 1) {
#pragma unroll
                for (int e = 0; e < HCH; ++e)
                    xppv[e] = att1 * (S[e] + attsum * xq[i][e]);
            } else {
                const float aa = att1 * attv[p];
#pragma unroll
                for (int e = 0; e < HCH; ++e)
                    xppv[e] = aa * (dp1v[e] + xq[i][e]);
            }

            float gsum = sB_gate[p];
            const float* xh = (p < 4) ? xhU : xhL;
#pragma unroll
            for (int e = 0; e < HCH; ++e)
                gsum += sW_gate[p * 2 * HCH + e] * xh[e];
#pragma unroll
            for (int e = 0; e < HCH; ++e)
                gsum += sW_gate[p * 2 * HCH + HCH + e] * xq[i][e];
            const float gate = sigm(gsum);

            float xhpv[HCH];
#pragma unroll
            for (int e = 0; e < HCH; ++e)
                xhpv[e] = gate * Dp[HCH + p * HCH + e];   // bias folded

            float* o0 = out + p * PBH + bbase;
#pragma unroll
            for (int e = 0; e < HCH; ++e) {
                float u = sB_upd[p * HCH + e];
                const float* wr = sW_upd + (p * HCH + e) * (3 * HCH);
#pragma unroll
                for (int f = 0; f < HCH; ++f) u += wr[f] * xq[i][f];
#pragma unroll
                for (int f = 0; f < HCH; ++f) u += wr[HCH + f] * xppv[f];
#pragma unroll
                for (int f = 0; f < HCH; ++f) u += wr[2 * HCH + f] * xhpv[f];
                const float o = xq[i][e] + fmaxf(u, 0.f);

                const int doff = e * HWDIM;
                o0[doff]               = o;
                o0[PART_SZ + doff]     = xppv[e];
                o0[2 * PART_SZ + doff] = xhpv[e];
            }
        }
    }
}

// ---------------------------------------------------------------------------
extern "C" void kernel_launch(void* const* d_in, const int* in_sizes, int n_in,
                              void* d_out, int out_size) {
    const float* p_fea  = (const float*)d_in[0];
    const float* xp     = (const float*)d_in[1];
    const float* xh     = (const float*)d_in[2];
    const float* w_att  = (const float*)d_in[3];
    const float* b_att  = (const float*)d_in[4];
    const float* w_dp_f = (const float*)d_in[5];
    const float* w_dp_x = (const float*)d_in[6];
    const float* b_dp   = (const float*)d_in[7];
    const float* w_proj = (const float*)d_in[8];
    const float* b_proj = (const float*)d_in[9];
    const float* w_gate = (const float*)d_in[10];
    const float* b_gate = (const float*)d_in[11];
    const float* w_upd  = (const float*)d_in[12];
    const float* b_upd  = (const float*)d_in[13];
    float* out = (float*)d_out;

    cudaFuncSetAttribute(fused_kernel, cudaFuncAttributeMaxDynamicSharedMemorySize,
                         FUSED_SMEM);

    prep_kernel<<<72, 256>>>(w_dp_f, w_proj, b_dp, b_proj);
    fused_kernel<<<NPOS / 128, 256, FUSED_SMEM>>>(
        p_fea, xp, xh, w_att, b_att, w_dp_x, w_gate, b_gate, w_upd, b_upd, out);
}